// round 7
// baseline (speedup 1.0000x reference)
#include <cuda_runtime.h>
#include <cuda_bf16.h>
#include <cstdint>
#include <math.h>

// Problem dims
#define BSZ   16
#define HH    64
#define WWID  64
#define CDIM  512
#define NHEAD 8
#define DKK   64
#define DVV   64
#define PIX   4096
#define MROWS 65536

// ---------------- scratch (device globals; no runtime allocation) ----------
__device__ float g_partial[BSZ * 32 * CDIM];
__device__ float g_qW[BSZ * NHEAD * CDIM];
__device__ float g_S[BSZ * NHEAD * PIX];
__device__ float g_ah[BSZ * HH * NHEAD * WWID];          // [b][h][n][w]
__device__ float g_av[BSZ * WWID * NHEAD * HH];          // [b][w][n][h]
__device__ __nv_bfloat16 g_yext[(size_t)16 * 1024 * 1536];   // [(path*8+n)][b*64+s][yhi|ylo|yhi]
__device__ __nv_bfloat16 g_wvext[NHEAD * 1536 * 64];         // [n][Whi;Whi;Wlo][v]
__device__ float g_Ahv2[2 * NHEAD * 1024 * DVV];             // [path][n][b*64+s][v]
__device__ __nv_bfloat16 g_Aext[(size_t)MROWS * 192];        // [Ahi | Alo | Ahi]
__device__ __nv_bfloat16 g_Wext[192 * 512];                  // [Whi ; Whi ; Wlo]

__device__ __forceinline__ uint32_t smem_u32(const void* p) {
    uint32_t a;
    asm("{ .reg .u64 t; cvta.to.shared.u64 t, %1; cvt.u32.u64 %0, t; }"
        : "=r"(a) : "l"(p));
    return a;
}
__device__ __forceinline__ uint2 pack4_hi(float4 v) {
    __nv_bfloat162 a(__float2bfloat16(v.x), __float2bfloat16(v.y));
    __nv_bfloat162 b(__float2bfloat16(v.z), __float2bfloat16(v.w));
    uint2 r;
    r.x = *(uint32_t*)&a;
    r.y = *(uint32_t*)&b;
    return r;
}
__device__ __forceinline__ uint2 pack4_lo(float4 v) {
    float lx = v.x - __bfloat162float(__float2bfloat16(v.x));
    float ly = v.y - __bfloat162float(__float2bfloat16(v.y));
    float lz = v.z - __bfloat162float(__float2bfloat16(v.z));
    float lw = v.w - __bfloat162float(__float2bfloat16(v.w));
    __nv_bfloat162 a(__float2bfloat16(lx), __float2bfloat16(ly));
    __nv_bfloat162 b(__float2bfloat16(lz), __float2bfloat16(lw));
    uint2 r;
    r.x = *(uint32_t*)&a;
    r.y = *(uint32_t*)&b;
    return r;
}

// ---------------- 1) spatial mean pooling ----------------------------------
__global__ __launch_bounds__(512) void pool_kernel(const float* __restrict__ x) {
    int b = blockIdx.x, j = blockIdx.y, c = threadIdx.x;
    const float* xp = x + ((size_t)b * PIX + (size_t)j * 128) * CDIM + c;
    float s = 0.f;
#pragma unroll 8
    for (int p = 0; p < 128; p++) s += xp[(size_t)p * CDIM];
    g_partial[(b * 32 + j) * CDIM + c] = s;
}

// ---------------- 2) q + qW fused -------------------------------------------
__global__ __launch_bounds__(512) void qqw_kernel(
    const float* __restrict__ Wq, const float* __restrict__ bq,
    const float* __restrict__ Wk)
{
    int b = blockIdx.x, t = threadIdx.x;
    __shared__ float sp[CDIM];
    __shared__ float sq[CDIM];
    float s = 0.f;
#pragma unroll
    for (int j = 0; j < 32; j++) s += g_partial[(b * 32 + j) * CDIM + t];
    sp[t] = s * (1.0f / 4096.0f);
    __syncthreads();
    float acc = bq[t];
#pragma unroll 8
    for (int c = 0; c < CDIM; c++) acc += sp[c] * Wq[c * 512 + t];
    sq[t] = acc;
    __syncthreads();
    // qW[b,n,t] = 0.125 * sum_k Wk[t, n*64+k] * sq[n*64+k]
    const float* wr = Wk + (size_t)t * 512;
    float a[8] = {0.f, 0.f, 0.f, 0.f, 0.f, 0.f, 0.f, 0.f};
#pragma unroll
    for (int n = 0; n < 8; n++)
#pragma unroll 8
        for (int k = 0; k < 64; k++)
            a[n] += sq[n * 64 + k] * wr[n * 64 + k];
#pragma unroll
    for (int n = 0; n < 8; n++)
        g_qW[(b * 8 + n) * 512 + t] = a[n] * 0.125f;
}

// ---------------- 3) prep: build g_wvext and g_Wext -------------------------
// grid 704: [0,512) -> wvext row c; [512,704) -> Wext row (r-512). 512 thr.
__global__ __launch_bounds__(512) void prep_kernel(
    const float* __restrict__ Wv, const float* __restrict__ Wo)
{
    int r = blockIdx.x, t = threadIdx.x;
    if (r < 512) {
        int c = r;
        int n = t >> 6, v = t & 63;
        float val = Wv[(size_t)c * 512 + t];
        __nv_bfloat16 hi = __float2bfloat16(val);
        __nv_bfloat16 lo = __float2bfloat16(val - __bfloat162float(hi));
        __nv_bfloat16* base = g_wvext + (size_t)n * 1536 * 64;
        base[(size_t)c * 64 + v] = hi;
        base[(size_t)(512 + c) * 64 + v] = hi;
        base[(size_t)(1024 + c) * 64 + v] = lo;
    } else {
        int rr = r - 512;
        int src = (rr < 128) ? (rr & 63) : (rr - 128);
        float v = Wo[(size_t)src * 512 + t];
        __nv_bfloat16 hi = __float2bfloat16(v);
        g_Wext[rr * 512 + t] = (rr < 128) ? hi
            : __float2bfloat16(v - __bfloat162float(hi));
    }
}

// ---------------- 4) scores: thread-per-pixel, smem-staged x ----------------
__global__ __launch_bounds__(256) void score_kernel(const float* __restrict__ x) {
    extern __shared__ float sdyn[];
    float* sqw = sdyn;            // [8][512]
    float* xs  = sdyn + 4096;     // [256][68]
    int b = blockIdx.x, tid = threadIdx.x;
    int p0 = blockIdx.y * 256;

    for (int i = tid; i < 4096; i += 256)
        sqw[i] = g_qW[(size_t)b * 4096 + i];

    float acc[8] = {0.f, 0.f, 0.f, 0.f, 0.f, 0.f, 0.f, 0.f};

    for (int ch = 0; ch < 8; ch++) {
        __syncthreads();
#pragma unroll
        for (int i = 0; i < 16; i++) {
            int idx = tid + i * 256;
            int p = idx >> 4, c4 = idx & 15;
            *(float4*)(xs + p * 68 + c4 * 4) =
                *(const float4*)(x + ((size_t)b * PIX + p0 + p) * CDIM + ch * 64 + c4 * 4);
        }
        __syncthreads();
#pragma unroll 4
        for (int c4 = 0; c4 < 16; c4++) {
            float4 xv = *(const float4*)(xs + tid * 68 + c4 * 4);
#pragma unroll
            for (int n = 0; n < 8; n++) {
                float4 w = *(const float4*)(sqw + n * 512 + ch * 64 + c4 * 4);
                acc[n] += xv.x * w.x + xv.y * w.y + xv.z * w.z + xv.w * w.w;
            }
        }
    }
#pragma unroll
    for (int n = 0; n < 8; n++)
        g_S[(size_t)(b * 8 + n) * PIX + p0 + tid] = acc[n];
}

// ---------------- 5) dual softmax per (b,n) ---------------------------------
__global__ __launch_bounds__(256) void softmax_kernel() {
    int bn = blockIdx.x;
    int b = bn >> 3, n = bn & 7;
    int tid = threadIdx.x, w = tid >> 5, l = tid & 31;
    __shared__ float ss[4096];
    for (int i = tid; i < 4096; i += 256) ss[i] = g_S[(size_t)bn * 4096 + i];
    __syncthreads();

    for (int h = w; h < 64; h += 8) {
        float x0 = ss[h * 64 + l], x1 = ss[h * 64 + 32 + l];
        float m = fmaxf(x0, x1);
#pragma unroll
        for (int o = 16; o > 0; o >>= 1)
            m = fmaxf(m, __shfl_xor_sync(0xffffffffu, m, o));
        float e0 = __expf(x0 - m), e1 = __expf(x1 - m);
        float sum = e0 + e1;
#pragma unroll
        for (int o = 16; o > 0; o >>= 1)
            sum += __shfl_xor_sync(0xffffffffu, sum, o);
        float inv = 1.0f / sum;
        float* dst = g_ah + ((size_t)(b * 64 + h) * 8 + n) * 64;
        dst[l] = e0 * inv;
        dst[32 + l] = e1 * inv;
    }

    if (tid < 64) {
        int c = tid;
        float m = -1e30f;
#pragma unroll 8
        for (int h = 0; h < 64; h++) m = fmaxf(m, ss[h * 64 + c]);
        float sum = 0.f;
#pragma unroll 8
        for (int h = 0; h < 64; h++) sum += __expf(ss[h * 64 + c] - m);
        float inv = 1.0f / sum;
        float* dst = g_av + ((size_t)(b * 64 + c) * 8 + n) * 64;
#pragma unroll 8
        for (int h = 0; h < 64; h++)
            dst[h] = __expf(ss[h * 64 + c] - m) * inv;
    }
}

// ---------------- 6) y_h / y_v -> bf16 [hi|lo|hi] ---------------------------
__global__ __launch_bounds__(128) void y_kernel(const float* __restrict__ x) {
    int b = blockIdx.x, s = blockIdx.y, path = blockIdx.z;
    int tid = threadIdx.x;
    __shared__ float sa[512];
    const float* asrc = (path ? g_av : g_ah) + (size_t)(b * 64 + s) * 512;
    for (int i = tid; i < 512; i += 128) sa[i] = asrc[i];
    __syncthreads();

    size_t base = (size_t)b * PIX * CDIM +
                  (path ? (size_t)s * CDIM : (size_t)s * 64 * CDIM);
    size_t stride4 = (path ? (size_t)64 * CDIM : (size_t)CDIM) / 4;
    const float4* xp = (const float4*)(x) + base / 4 + tid;

    float4 acc[8];
#pragma unroll
    for (int n = 0; n < 8; n++) acc[n] = make_float4(0.f, 0.f, 0.f, 0.f);

#pragma unroll 8
    for (int j = 0; j < 64; j++) {
        float4 xv = xp[j * stride4];
#pragma unroll
        for (int n = 0; n < 8; n++) {
            float f = sa[n * 64 + j];
            acc[n].x += f * xv.x;
            acc[n].y += f * xv.y;
            acc[n].z += f * xv.z;
            acc[n].w += f * xv.w;
        }
    }
    int c = tid * 4;
#pragma unroll
    for (int n = 0; n < 8; n++) {
        size_t row = (size_t)(path * 8 + n) * 1024 + b * 64 + s;
        __nv_bfloat16* dst = g_yext + row * 1536;
        uint2 hi = pack4_hi(acc[n]);
        uint2 lo = pack4_lo(acc[n]);
        *(uint2*)(dst + c)        = hi;
        *(uint2*)(dst + 512 + c)  = lo;
        *(uint2*)(dst + 1024 + c) = hi;
    }
}

// ---------------- 7) aproj via mma.sync: A = Yext @ Wvext + bv --------------
// grid (16 mtiles, 8 heads, 2 paths); 128 thr = 4 warps (16-row warp tiles).
__global__ __launch_bounds__(128) void aproj_mma(const float* __restrict__ bv) {
    __shared__ __align__(16) __nv_bfloat16 smA[64 * 72];
    __shared__ __align__(16) __nv_bfloat16 smB[64 * 72];
    int tid = threadIdx.x, lane = tid & 31, wm = tid >> 5;
    int mt = blockIdx.x, n = blockIdx.y, path = blockIdx.z;

    const __nv_bfloat16* Abase =
        g_yext + ((size_t)(path * 8 + n) * 1024 + mt * 64) * 1536;
    const __nv_bfloat16* Bbase = g_wvext + (size_t)n * 1536 * 64;

    float acc[8][4];
#pragma unroll
    for (int i = 0; i < 8; i++)
#pragma unroll
        for (int j = 0; j < 4; j++) acc[i][j] = 0.f;

    for (int kc = 0; kc < 24; kc++) {
#pragma unroll
        for (int i = 0; i < 4; i++) {
            int idx = tid + i * 128;
            int r = idx >> 3, c8 = idx & 7;
            *(float4*)(smA + r * 72 + c8 * 8) =
                *(const float4*)(Abase + (size_t)r * 1536 + kc * 64 + c8 * 8);
            *(float4*)(smB + r * 72 + c8 * 8) =
                *(const float4*)(Bbase + (size_t)(kc * 64 + r) * 64 + c8 * 8);
        }
        __syncthreads();

#pragma unroll
        for (int ks = 0; ks < 4; ks++) {
            uint32_t af[4];
            {
                uint32_t addr = smem_u32(
                    smA + (wm * 16 + (lane & 15)) * 72 + ks * 16 + (lane >> 4) * 8);
                asm volatile(
                    "ldmatrix.sync.aligned.m8n8.x4.shared.b16 {%0,%1,%2,%3}, [%4];"
                    : "=r"(af[0]), "=r"(af[1]), "=r"(af[2]), "=r"(af[3])
                    : "r"(addr));
            }
            uint32_t bfr[4][4];
#pragma unroll
            for (int bi = 0; bi < 4; bi++) {
                uint32_t addr = smem_u32(
                    smB + (ks * 16 + (lane & 15)) * 72 + bi * 16 + (lane >> 4) * 8);
                asm volatile(
                    "ldmatrix.sync.aligned.m8n8.x4.trans.shared.b16 {%0,%1,%2,%3}, [%4];"
                    : "=r"(bfr[bi][0]), "=r"(bfr[bi][1]),
                      "=r"(bfr[bi][2]), "=r"(bfr[bi][3])
                    : "r"(addr));
            }
#pragma unroll
            for (int ni = 0; ni < 8; ni++) {
                uint32_t b0 = bfr[ni >> 1][(ni & 1) * 2];
                uint32_t b1 = bfr[ni >> 1][(ni & 1) * 2 + 1];
                asm volatile(
                    "mma.sync.aligned.m16n8k16.row.col.f32.bf16.bf16.f32 "
                    "{%0,%1,%2,%3}, {%4,%5,%6,%7}, {%8,%9}, {%0,%1,%2,%3};"
                    : "+f"(acc[ni][0]), "+f"(acc[ni][1]),
                      "+f"(acc[ni][2]), "+f"(acc[ni][3])
                    : "r"(af[0]), "r"(af[1]), "r"(af[2]), "r"(af[3]),
                      "r"(b0), "r"(b1));
            }
        }
        __syncthreads();
    }

    int g = lane >> 2, t = lane & 3;
    float* outp = g_Ahv2 + ((size_t)(path * 8 + n) * 1024 + mt * 64) * 64;
#pragma unroll
    for (int ni = 0; ni < 8; ni++) {
        int col = ni * 8 + t * 2;
        float b0 = bv[n * 64 + col], b1 = bv[n * 64 + col + 1];
        int r0 = wm * 16 + g;
        *(float2*)(outp + (size_t)r0 * 64 + col) =
            make_float2(acc[ni][0] + b0, acc[ni][1] + b1);
        *(float2*)(outp + (size_t)(r0 + 8) * 64 + col) =
            make_float2(acc[ni][2] + b0, acc[ni][3] + b1);
    }
}

// ---------------- 8) combine -> Aext bf16 [hi|lo|hi] ------------------------
__global__ __launch_bounds__(512) void combine_kernel() {
    int b = blockIdx.x >> 6, h = blockIdx.x & 63;
    int tid = threadIdx.x;
    __shared__ float sAh[NHEAD * DVV];
    {
        int n = tid >> 6, v = tid & 63;
        sAh[tid] = g_Ahv2[((size_t)n * 1024 + b * 64 + h) * 64 + v];
    }
    __syncthreads();
    int v = tid & 63, wg = tid >> 6;
    const float* Avb = g_Ahv2 + (size_t)8 * 1024 * 64;
    for (int wc = wg; wc < 64; wc += 8) {
        float acc = 0.f;
#pragma unroll
        for (int n = 0; n < NHEAD; n++)
            acc += sAh[n * 64 + v] *
                   Avb[((size_t)n * 1024 + b * 64 + wc) * 64 + v];
        size_t row = ((size_t)(b * 64 + h)) * 64 + wc;
        __nv_bfloat16 hi = __float2bfloat16(acc);
        __nv_bfloat16 lo = __float2bfloat16(acc - __bfloat162float(hi));
        g_Aext[row * 192 + v]       = hi;
        g_Aext[row * 192 + 64 + v]  = lo;
        g_Aext[row * 192 + 128 + v] = hi;
    }
}

// ---------------- 9) bf16 mma.sync GEMM: out = Aext @ Wext + bias -----------
__global__ __launch_bounds__(256) void mma_gemm_out(
    const float* __restrict__ bias, float* __restrict__ C)
{
    __shared__ __align__(16) __nv_bfloat16 smA[128 * 72];
    __shared__ __align__(16) __nv_bfloat16 smB[64 * 136];
    int tid = threadIdx.x, lane = tid & 31, wid = tid >> 5;
    int wm = wid >> 2, wn = wid & 3;
    size_t m0 = (size_t)blockIdx.y * 128;
    int n0 = blockIdx.x * 128;

    float acc[4][4][4];
#pragma unroll
    for (int i = 0; i < 4; i++)
#pragma unroll
        for (int j = 0; j < 4; j++)
#pragma unroll
            for (int k = 0; k < 4; k++) acc[i][j][k] = 0.f;

    // register prefetch pipeline over 3 K-chunks
    float4 pa[4], pb[4];
#pragma unroll
    for (int i = 0; i < 4; i++) {
        int idx = tid + i * 256;
        int r = idx >> 3, c8 = idx & 7;
        pa[i] = *(const float4*)(g_Aext + (m0 + r) * 192 + c8 * 8);
        int rb = idx >> 4, cb8 = idx & 15;
        pb[i] = *(const float4*)(g_Wext + (size_t)rb * 512 + n0 + cb8 * 8);
    }

    for (int kc = 0; kc < 192; kc += 64) {
#pragma unroll
        for (int i = 0; i < 4; i++) {
            int idx = tid + i * 256;
            int r = idx >> 3, c8 = idx & 7;
            *(float4*)(smA + r * 72 + c8 * 8) = pa[i];
            int rb = idx >> 4, cb8 = idx & 15;
            *(float4*)(smB + rb * 136 + cb8 * 8) = pb[i];
        }
        __syncthreads();
        if (kc < 128) {
#pragma unroll
            for (int i = 0; i < 4; i++) {
                int idx = tid + i * 256;
                int r = idx >> 3, c8 = idx & 7;
                pa[i] = *(const float4*)(g_Aext + (m0 + r) * 192 + kc + 64 + c8 * 8);
                int rb = idx >> 4, cb8 = idx & 15;
                pb[i] = *(const float4*)(g_Wext + (size_t)(kc + 64 + rb) * 512 + n0 + cb8 * 8);
            }
        }

#pragma unroll
        for (int ks = 0; ks < 4; ks++) {
            uint32_t af[4][4];
#pragma unroll
            for (int mi = 0; mi < 4; mi++) {
                uint32_t addr = smem_u32(
                    smA + (wm * 64 + mi * 16 + (lane & 15)) * 72 +
                    ks * 16 + (lane >> 4) * 8);
                asm volatile(
                    "ldmatrix.sync.aligned.m8n8.x4.shared.b16 {%0,%1,%2,%3}, [%4];"
                    : "=r"(af[mi][0]), "=r"(af[mi][1]),
                      "=r"(af[mi][2]), "=r"(af[mi][3])
                    : "r"(addr));
            }
            uint32_t bfr[2][4];
#pragma unroll
            for (int bi = 0; bi < 2; bi++) {
                int nb = wn * 32 + bi * 16;
                uint32_t addr = smem_u32(
                    smB + (ks * 16 + (lane & 15)) * 136 + nb + (lane >> 4) * 8);
                asm volatile(
                    "ldmatrix.sync.aligned.m8n8.x4.trans.shared.b16 {%0,%1,%2,%3}, [%4];"
                    : "=r"(bfr[bi][0]), "=r"(bfr[bi][1]),
                      "=r"(bfr[bi][2]), "=r"(bfr[bi][3])
                    : "r"(addr));
            }
#pragma unroll
            for (int mi = 0; mi < 4; mi++) {
#pragma unroll
                for (int ni = 0; ni < 4; ni++) {
                    uint32_t b0 = bfr[ni >> 1][(ni & 1) * 2];
                    uint32_t b1 = bfr[ni >> 1][(ni & 1) * 2 + 1];
                    asm volatile(
                        "mma.sync.aligned.m16n8k16.row.col.f32.bf16.bf16.f32 "
                        "{%0,%1,%2,%3}, {%4,%5,%6,%7}, {%8,%9}, {%0,%1,%2,%3};"
                        : "+f"(acc[mi][ni][0]), "+f"(acc[mi][ni][1]),
                          "+f"(acc[mi][ni][2]), "+f"(acc[mi][ni][3])
                        : "r"(af[mi][0]), "r"(af[mi][1]),
                          "r"(af[mi][2]), "r"(af[mi][3]),
                          "r"(b0), "r"(b1));
                }
            }
        }
        __syncthreads();
    }

    int g = lane >> 2, t = lane & 3;
#pragma unroll
    for (int mi = 0; mi < 4; mi++) {
#pragma unroll
        for (int ni = 0; ni < 4; ni++) {
            size_t row = m0 + wm * 64 + mi * 16 + g;
            int col = n0 + wn * 32 + ni * 8 + t * 2;
            float b0 = bias[col], b1 = bias[col + 1];
            float2 o0 = {acc[mi][ni][0] + b0, acc[mi][ni][1] + b1};
            float2 o1 = {acc[mi][ni][2] + b0, acc[mi][ni][3] + b1};
            *(float2*)(C + row * 512 + col) = o0;
            *(float2*)(C + (row + 8) * 512 + col) = o1;
        }
    }
}

// ---------------- launch ----------------------------------------------------
extern "C" void kernel_launch(void* const* d_in, const int* in_sizes, int n_in,
                              void* d_out, int out_size) {
    const float* x  = (const float*)d_in[0];
    const float* Wq = (const float*)d_in[1];
    const float* bq = (const float*)d_in[2];
    const float* Wk = (const float*)d_in[3];
    const float* bk = (const float*)d_in[4];  (void)bk;  // cancels in softmax
    const float* Wv = (const float*)d_in[5];
    const float* bv = (const float*)d_in[6];
    const float* Wo = (const float*)d_in[7];
    const float* bo = (const float*)d_in[8];
    float* out = (float*)d_out;

    const int SCORE_SMEM = (4096 + 256 * 68) * 4;
    cudaFuncSetAttribute(score_kernel,
                         cudaFuncAttributeMaxDynamicSharedMemorySize, SCORE_SMEM);

    pool_kernel<<<dim3(BSZ, 32), 512>>>(x);
    qqw_kernel<<<BSZ, 512>>>(Wq, bq, Wk);
    prep_kernel<<<704, 512>>>(Wv, Wo);
    score_kernel<<<dim3(BSZ, 16), 256, SCORE_SMEM>>>(x);
    softmax_kernel<<<BSZ * NHEAD, 256>>>();
    y_kernel<<<dim3(BSZ, 64, 2), 128>>>(x);
    aproj_mma<<<dim3(16, NHEAD, 2), 128>>>(bv);
    combine_kernel<<<BSZ * HH, 512>>>();
    mma_gemm_out<<<dim3(4, 512), 256>>>(bo, out);
}

// round 8
// speedup vs baseline: 1.3935x; 1.3935x over previous
#include <cuda_runtime.h>
#include <cuda_bf16.h>
#include <cstdint>
#include <math.h>

// Problem dims
#define BSZ   16
#define HH    64
#define WWID  64
#define CDIM  512
#define NHEAD 8
#define DKK   64
#define DVV   64
#define PIX   4096
#define MROWS 65536

// ---------------- scratch (device globals; no runtime allocation) ----------
__device__ float g_partial[BSZ * 32 * CDIM];
__device__ float g_q[BSZ * NHEAD * DKK];
__device__ float g_qW[BSZ * NHEAD * CDIM];
__device__ float g_S[BSZ * NHEAD * PIX];
__device__ float g_ah[BSZ * HH * NHEAD * WWID];
__device__ float g_av[BSZ * WWID * NHEAD * HH];
__device__ float g_yh[(size_t)NHEAD * BSZ * HH * CDIM];
__device__ float g_yv[(size_t)NHEAD * BSZ * WWID * CDIM];
__device__ float g_Ah[BSZ * NHEAD * HH * DVV];
__device__ float g_Av[BSZ * NHEAD * WWID * DVV];
__device__ __nv_bfloat16 g_Aext[(size_t)MROWS * 192];  // [Ahi | Alo | Ahi]
__device__ __nv_bfloat16 g_Wext[192 * 512];            // [Whi ; Whi ; Wlo]

__device__ __forceinline__ uint32_t smem_u32(const void* p) {
    uint32_t a;
    asm("{ .reg .u64 t; cvta.to.shared.u64 t, %1; cvt.u32.u64 %0, t; }"
        : "=r"(a) : "l"(p));
    return a;
}

// ---------------- 1) spatial mean pooling ----------------------------------
__global__ __launch_bounds__(512) void pool_kernel(const float* __restrict__ x) {
    int b = blockIdx.x, j = blockIdx.y, c = threadIdx.x;
    const float* xp = x + ((size_t)b * PIX + (size_t)j * 128) * CDIM + c;
    float s = 0.f;
#pragma unroll 8
    for (int p = 0; p < 128; p++) s += xp[(size_t)p * CDIM];
    g_partial[(b * 32 + j) * CDIM + c] = s;
}

// ---------------- 2) q = pooled @ Wq + bq -----------------------------------
__global__ void q_kernel(const float* __restrict__ Wq, const float* __restrict__ bq) {
    int b = blockIdx.x, t = threadIdx.x;
    __shared__ float sp[CDIM];
    float s = 0.f;
#pragma unroll
    for (int j = 0; j < 32; j++) s += g_partial[(b * 32 + j) * CDIM + t];
    sp[t] = s * (1.0f / 4096.0f);
    __syncthreads();
    float acc = bq[t];
#pragma unroll 8
    for (int c = 0; c < CDIM; c++) acc += sp[c] * Wq[c * 512 + t];
    g_q[b * 512 + t] = acc;
}

// ---------------- 3) qW[b,n,c] = scale * sum_k Wk[c, n*64+k] q[b,n,k] ------
__global__ void qw_kernel(const float* __restrict__ Wk) {
    int b = blockIdx.x, n = blockIdx.y, c = threadIdx.x;
    __shared__ float sq[64];
    if (c < 64) sq[c] = g_q[b * 512 + n * 64 + c];
    __syncthreads();
    const float* wr = Wk + (size_t)c * 512 + n * 64;
    float acc = 0.f;
#pragma unroll
    for (int k = 0; k < 64; k++) acc += sq[k] * wr[k];
    g_qW[(b * 8 + n) * 512 + c] = acc * 0.125f;
}

// ---------------- 4) scores: 128 px/block, 32-col chunks, high occupancy ---
__global__ __launch_bounds__(128) void score_kernel(const float* __restrict__ x) {
    extern __shared__ float sdyn[];
    float* sqw = sdyn;            // [8][512] = 16KB
    float* xs  = sdyn + 4096;     // [128][36] = 18KB (pad 4: conflict-free LDS.128)
    int b = blockIdx.x, tid = threadIdx.x;
    int p0 = blockIdx.y * 128;

    for (int i = tid; i < 4096; i += 128)
        sqw[i] = g_qW[(size_t)b * 4096 + i];

    float acc[8] = {0.f, 0.f, 0.f, 0.f, 0.f, 0.f, 0.f, 0.f};

    for (int ch = 0; ch < 16; ch++) {
        __syncthreads();
        // stage x[p0..p0+127][ch*32..+32] -> xs (8 thr cover 128B of one row)
#pragma unroll
        for (int i = 0; i < 8; i++) {
            int idx = tid + i * 128;
            int p = idx >> 3, c4 = idx & 7;
            *(float4*)(xs + p * 36 + c4 * 4) =
                *(const float4*)(x + ((size_t)b * PIX + p0 + p) * CDIM + ch * 32 + c4 * 4);
        }
        __syncthreads();
#pragma unroll
        for (int c4 = 0; c4 < 8; c4++) {
            float4 xv = *(const float4*)(xs + tid * 36 + c4 * 4);
#pragma unroll
            for (int n = 0; n < 8; n++) {
                float4 w = *(const float4*)(sqw + n * 512 + ch * 32 + c4 * 4);
                acc[n] += xv.x * w.x + xv.y * w.y + xv.z * w.z + xv.w * w.w;
            }
        }
    }
#pragma unroll
    for (int n = 0; n < 8; n++)
        g_S[(size_t)(b * 8 + n) * PIX + p0 + tid] = acc[n];
}

// ---------------- 5) dual softmax per (b,n), write transposed layouts ------
__global__ __launch_bounds__(256) void softmax_kernel() {
    int bn = blockIdx.x;
    int b = bn >> 3, n = bn & 7;
    int tid = threadIdx.x, w = tid >> 5, l = tid & 31;
    __shared__ float ss[4096];
    for (int i = tid; i < 4096; i += 256) ss[i] = g_S[(size_t)bn * 4096 + i];
    __syncthreads();

    for (int h = w; h < 64; h += 8) {
        float x0 = ss[h * 64 + l], x1 = ss[h * 64 + 32 + l];
        float m = fmaxf(x0, x1);
#pragma unroll
        for (int o = 16; o > 0; o >>= 1)
            m = fmaxf(m, __shfl_xor_sync(0xffffffffu, m, o));
        float e0 = __expf(x0 - m), e1 = __expf(x1 - m);
        float sum = e0 + e1;
#pragma unroll
        for (int o = 16; o > 0; o >>= 1)
            sum += __shfl_xor_sync(0xffffffffu, sum, o);
        float inv = 1.0f / sum;
        float* dst = g_ah + ((size_t)(b * 64 + h) * 8 + n) * 64;
        dst[l] = e0 * inv;
        dst[32 + l] = e1 * inv;
    }

    if (tid < 64) {
        int c = tid;
        float m = -1e30f;
#pragma unroll 8
        for (int h = 0; h < 64; h++) m = fmaxf(m, ss[h * 64 + c]);
        float sum = 0.f;
#pragma unroll 8
        for (int h = 0; h < 64; h++) sum += __expf(ss[h * 64 + c] - m);
        float inv = 1.0f / sum;
        float* dst = g_av + ((size_t)(b * 64 + c) * 8 + n) * 64;
#pragma unroll 8
        for (int h = 0; h < 64; h++)
            dst[h] = __expf(ss[h * 64 + c] - m) * inv;
    }
}

// ---------------- 6) y_h / y_v: weighted sums of x rows --------------------
__global__ __launch_bounds__(128) void y_kernel(const float* __restrict__ x) {
    int b = blockIdx.x, s = blockIdx.y, path = blockIdx.z;
    int tid = threadIdx.x;
    __shared__ float sa[512];
    const float* asrc = (path ? g_av : g_ah) + (size_t)(b * 64 + s) * 512;
    for (int i = tid; i < 512; i += 128) sa[i] = asrc[i];
    __syncthreads();

    size_t base = (size_t)b * PIX * CDIM +
                  (path ? (size_t)s * CDIM : (size_t)s * 64 * CDIM);
    size_t stride4 = (path ? (size_t)64 * CDIM : (size_t)CDIM) / 4;
    const float4* xp = (const float4*)(x) + base / 4 + tid;

    float4 acc[8];
#pragma unroll
    for (int n = 0; n < 8; n++) acc[n] = make_float4(0.f, 0.f, 0.f, 0.f);

#pragma unroll 8
    for (int j = 0; j < 64; j++) {
        float4 xv = xp[j * stride4];
#pragma unroll
        for (int n = 0; n < 8; n++) {
            float f = sa[n * 64 + j];
            acc[n].x += f * xv.x;
            acc[n].y += f * xv.y;
            acc[n].z += f * xv.z;
            acc[n].w += f * xv.w;
        }
    }
    float* yout = path ? g_yv : g_yh;
#pragma unroll
    for (int n = 0; n < 8; n++)
        ((float4*)(yout + ((size_t)(n * 1024 + b * 64 + s)) * 512))[tid] = acc[n];
}

// ---------------- 7) project y -> A_h / A_v (per-head 64-col GEMM) ---------
__global__ __launch_bounds__(256) void aproj_kernel(
    const float* __restrict__ Wv, const float* __restrict__ bv)
{
    int n = blockIdx.x, b = blockIdx.y, path = blockIdx.z;
    const float* Y = (path ? g_yv : g_yh) + ((size_t)(n * 1024 + b * 64)) * 512;
    float* outp = (path ? g_Av : g_Ah) + (size_t)(b * 8 + n) * 4096;
    __shared__ float sY[64][32];
    __shared__ float sW[32][64];
    int tid = threadIdx.x;
    int tr = tid >> 4, tc = tid & 15;
    float acc[4][4];
#pragma unroll
    for (int i = 0; i < 4; i++)
#pragma unroll
        for (int j = 0; j < 4; j++) acc[i][j] = 0.f;

    for (int k0 = 0; k0 < 512; k0 += 32) {
        for (int i = tid; i < 512; i += 256) {
            int r = i >> 3, c4 = i & 7;
            *(float4*)&sY[r][c4 * 4] =
                *(const float4*)(Y + (size_t)r * 512 + k0 + c4 * 4);
        }
        for (int i = tid; i < 512; i += 256) {
            int r = i >> 4, c4 = i & 15;
            *(float4*)&sW[r][c4 * 4] =
                *(const float4*)(Wv + (size_t)(k0 + r) * 512 + n * 64 + c4 * 4);
        }
        __syncthreads();
#pragma unroll
        for (int k = 0; k < 32; k++) {
            float4 bw = *(float4*)&sW[k][tc * 4];
            float a0 = sY[tr * 4 + 0][k], a1 = sY[tr * 4 + 1][k];
            float a2 = sY[tr * 4 + 2][k], a3 = sY[tr * 4 + 3][k];
            acc[0][0] += a0 * bw.x; acc[0][1] += a0 * bw.y; acc[0][2] += a0 * bw.z; acc[0][3] += a0 * bw.w;
            acc[1][0] += a1 * bw.x; acc[1][1] += a1 * bw.y; acc[1][2] += a1 * bw.z; acc[1][3] += a1 * bw.w;
            acc[2][0] += a2 * bw.x; acc[2][1] += a2 * bw.y; acc[2][2] += a2 * bw.z; acc[2][3] += a2 * bw.w;
            acc[3][0] += a3 * bw.x; acc[3][1] += a3 * bw.y; acc[3][2] += a3 * bw.z; acc[3][3] += a3 * bw.w;
        }
        __syncthreads();
    }
    float bb[4];
#pragma unroll
    for (int j = 0; j < 4; j++) bb[j] = bv[n * 64 + tc * 4 + j];
#pragma unroll
    for (int i = 0; i < 4; i++)
#pragma unroll
        for (int j = 0; j < 4; j++)
            outp[(tr * 4 + i) * 64 + tc * 4 + j] = acc[i][j] + bb[j];
}

// ---------------- 8) Wext = [hi(Wo); hi(Wo); lo(Wo)] -----------------------
__global__ void wext_kernel(const float* __restrict__ Wo) {
    int r = blockIdx.x, n = threadIdx.x;
    int src = (r < 128) ? (r & 63) : (r - 128);
    float v = Wo[(size_t)src * 512 + n];
    __nv_bfloat16 hi = __float2bfloat16(v);
    g_Wext[r * 512 + n] = (r < 128) ? hi
                                    : __float2bfloat16(v - __bfloat162float(hi));
}

// ---------------- 9) combine -> Aext bf16 [hi|lo|hi] ------------------------
__global__ __launch_bounds__(512) void combine_kernel() {
    int b = blockIdx.x >> 6, h = blockIdx.x & 63;
    int tid = threadIdx.x;
    __shared__ float sAh[NHEAD * DVV];
    {
        int n = tid >> 6, v = tid & 63;
        sAh[tid] = g_Ah[((size_t)(b * 8 + n) * 64 + h) * 64 + v];
    }
    __syncthreads();
    int v = tid & 63, wg = tid >> 6;
    for (int wc = wg; wc < 64; wc += 8) {
        float acc = 0.f;
#pragma unroll
        for (int n = 0; n < NHEAD; n++)
            acc += sAh[n * 64 + v] *
                   g_Av[((size_t)(b * 8 + n) * 64 + wc) * 64 + v];
        size_t row = ((size_t)(b * 64 + h)) * 64 + wc;
        __nv_bfloat16 hi = __float2bfloat16(acc);
        __nv_bfloat16 lo = __float2bfloat16(acc - __bfloat162float(hi));
        g_Aext[row * 192 + v]       = hi;
        g_Aext[row * 192 + 64 + v]  = lo;
        g_Aext[row * 192 + 128 + v] = hi;
    }
}

// ---------------- 10) bf16 mma.sync GEMM: C = Aext @ Wext + bias -----------
__global__ __launch_bounds__(256) void mma_gemm_out(
    const float* __restrict__ bias, float* __restrict__ C)
{
    __shared__ __align__(16) __nv_bfloat16 smA[128 * 72];
    __shared__ __align__(16) __nv_bfloat16 smB[64 * 136];
    int tid = threadIdx.x, lane = tid & 31, wid = tid >> 5;
    int wm = wid >> 2, wn = wid & 3;
    size_t m0 = (size_t)blockIdx.y * 128;
    int n0 = blockIdx.x * 128;

    float acc[4][4][4];
#pragma unroll
    for (int i = 0; i < 4; i++)
#pragma unroll
        for (int j = 0; j < 4; j++)
#pragma unroll
            for (int k = 0; k < 4; k++) acc[i][j][k] = 0.f;

    for (int kc = 0; kc < 192; kc += 64) {
#pragma unroll
        for (int i = 0; i < 4; i++) {
            int idx = tid + i * 256;
            int r = idx >> 3, c8 = idx & 7;
            *(float4*)(smA + r * 72 + c8 * 8) =
                *(const float4*)(g_Aext + (m0 + r) * 192 + kc + c8 * 8);
        }
#pragma unroll
        for (int i = 0; i < 4; i++) {
            int idx = tid + i * 256;
            int r = idx >> 4, c8 = idx & 15;
            *(float4*)(smB + r * 136 + c8 * 8) =
                *(const float4*)(g_Wext + (size_t)(kc + r) * 512 + n0 + c8 * 8);
        }
        __syncthreads();

#pragma unroll
        for (int ks = 0; ks < 4; ks++) {
            uint32_t af[4][4];
#pragma unroll
            for (int mi = 0; mi < 4; mi++) {
                uint32_t addr = smem_u32(
                    smA + (wm * 64 + mi * 16 + (lane & 15)) * 72 +
                    ks * 16 + (lane >> 4) * 8);
                asm volatile(
                    "ldmatrix.sync.aligned.m8n8.x4.shared.b16 {%0,%1,%2,%3}, [%4];"
                    : "=r"(af[mi][0]), "=r"(af[mi][1]),
                      "=r"(af[mi][2]), "=r"(af[mi][3])
                    : "r"(addr));
            }
            uint32_t bfr[2][4];
#pragma unroll
            for (int bi = 0; bi < 2; bi++) {
                int nb = wn * 32 + bi * 16;
                uint32_t addr = smem_u32(
                    smB + (ks * 16 + (lane & 7) + ((lane >> 3) & 1) * 8) * 136 +
                    nb + (lane >> 4) * 8);
                asm volatile(
                    "ldmatrix.sync.aligned.m8n8.x4.trans.shared.b16 {%0,%1,%2,%3}, [%4];"
                    : "=r"(bfr[bi][0]), "=r"(bfr[bi][1]),
                      "=r"(bfr[bi][2]), "=r"(bfr[bi][3])
                    : "r"(addr));
            }
#pragma unroll
            for (int mi = 0; mi < 4; mi++) {
#pragma unroll
                for (int ni = 0; ni < 4; ni++) {
                    uint32_t b0 = bfr[ni >> 1][(ni & 1) * 2];
                    uint32_t b1 = bfr[ni >> 1][(ni & 1) * 2 + 1];
                    asm volatile(
                        "mma.sync.aligned.m16n8k16.row.col.f32.bf16.bf16.f32 "
                        "{%0,%1,%2,%3}, {%4,%5,%6,%7}, {%8,%9}, {%0,%1,%2,%3};"
                        : "+f"(acc[mi][ni][0]), "+f"(acc[mi][ni][1]),
                          "+f"(acc[mi][ni][2]), "+f"(acc[mi][ni][3])
                        : "r"(af[mi][0]), "r"(af[mi][1]),
                          "r"(af[mi][2]), "r"(af[mi][3]),
                          "r"(b0), "r"(b1));
                }
            }
        }
        __syncthreads();
    }

    int g = lane >> 2, t = lane & 3;
#pragma unroll
    for (int mi = 0; mi < 4; mi++) {
#pragma unroll
        for (int ni = 0; ni < 4; ni++) {
            size_t row = m0 + wm * 64 + mi * 16 + g;
            int col = n0 + wn * 32 + ni * 8 + t * 2;
            float b0 = bias[col], b1 = bias[col + 1];
            float2 o0 = {acc[mi][ni][0] + b0, acc[mi][ni][1] + b1};
            float2 o1 = {acc[mi][ni][2] + b0, acc[mi][ni][3] + b1};
            *(float2*)(C + row * 512 + col) = o0;
            *(float2*)(C + (row + 8) * 512 + col) = o1;
        }
    }
}

// ---------------- launch ----------------------------------------------------
extern "C" void kernel_launch(void* const* d_in, const int* in_sizes, int n_in,
                              void* d_out, int out_size) {
    const float* x  = (const float*)d_in[0];
    const float* Wq = (const float*)d_in[1];
    const float* bq = (const float*)d_in[2];
    const float* Wk = (const float*)d_in[3];
    const float* bk = (const float*)d_in[4];  (void)bk;  // cancels in softmax
    const float* Wv = (const float*)d_in[5];
    const float* bv = (const float*)d_in[6];
    const float* Wo = (const float*)d_in[7];
    const float* bo = (const float*)d_in[8];
    float* out = (float*)d_out;

    const int SCORE_SMEM = (4096 + 128 * 36) * 4;   // 34816 B
    cudaFuncSetAttribute(score_kernel,
                         cudaFuncAttributeMaxDynamicSharedMemorySize, SCORE_SMEM);

    pool_kernel<<<dim3(BSZ, 32), 512>>>(x);
    q_kernel<<<BSZ, 512>>>(Wq, bq);
    qw_kernel<<<dim3(BSZ, NHEAD), 512>>>(Wk);
    wext_kernel<<<192, 512>>>(Wo);
    score_kernel<<<dim3(BSZ, 32), 128, SCORE_SMEM>>>(x);
    softmax_kernel<<<BSZ * NHEAD, 256>>>();
    y_kernel<<<dim3(BSZ, 64, 2), 128>>>(x);
    aproj_kernel<<<dim3(NHEAD, BSZ, 2), 256>>>(Wv, bv);
    combine_kernel<<<BSZ * HH, 512>>>();
    mma_gemm_out<<<dim3(4, 512), 256>>>(bo, out);
}

// round 9
// speedup vs baseline: 1.4881x; 1.0679x over previous
#include <cuda_runtime.h>
#include <cuda_bf16.h>
#include <cstdint>
#include <math.h>

// Problem dims
#define BSZ   16
#define HH    64
#define WWID  64
#define CDIM  512
#define NHEAD 8
#define DKK   64
#define DVV   64
#define PIX   4096
#define MROWS 65536

// ---------------- scratch (device globals; no runtime allocation) ----------
__device__ float g_partial[BSZ * 32 * CDIM];
__device__ float g_q[BSZ * NHEAD * DKK];
__device__ float g_qW[BSZ * NHEAD * CDIM];
__device__ float g_S[BSZ * NHEAD * PIX];
__device__ float g_ah[BSZ * HH * NHEAD * WWID];
__device__ float g_av[BSZ * WWID * NHEAD * HH];
__device__ float g_yh[(size_t)NHEAD * BSZ * HH * CDIM];
__device__ float g_yv[(size_t)NHEAD * BSZ * WWID * CDIM];
__device__ float g_Ah[BSZ * NHEAD * HH * DVV];
__device__ float g_Av[BSZ * NHEAD * WWID * DVV];
__device__ __nv_bfloat16 g_Aext[(size_t)MROWS * 192];  // [Ahi | Alo | Ahi]
__device__ __nv_bfloat16 g_Wext[192 * 512];            // [Whi ; Whi ; Wlo]

__device__ __forceinline__ uint32_t smem_u32(const void* p) {
    uint32_t a;
    asm("{ .reg .u64 t; cvta.to.shared.u64 t, %1; cvt.u32.u64 %0, t; }"
        : "=r"(a) : "l"(p));
    return a;
}
__device__ __forceinline__ uint32_t f2tf32(float f) {
    uint32_t r;
    asm("cvt.rna.tf32.f32 %0, %1;" : "=r"(r) : "f"(f));
    return r;
}
__device__ __forceinline__ void mma_tf32(
    float* c, const uint32_t* a, const uint32_t* b)
{
    asm volatile(
        "mma.sync.aligned.m16n8k8.row.col.f32.tf32.tf32.f32 "
        "{%0,%1,%2,%3}, {%4,%5,%6,%7}, {%8,%9}, {%0,%1,%2,%3};"
        : "+f"(c[0]), "+f"(c[1]), "+f"(c[2]), "+f"(c[3])
        : "r"(a[0]), "r"(a[1]), "r"(a[2]), "r"(a[3]), "r"(b[0]), "r"(b[1]));
}

// ---------------- 1) spatial mean pooling ----------------------------------
__global__ __launch_bounds__(512) void pool_kernel(const float* __restrict__ x) {
    int b = blockIdx.x, j = blockIdx.y, c = threadIdx.x;
    const float* xp = x + ((size_t)b * PIX + (size_t)j * 128) * CDIM + c;
    float s = 0.f;
#pragma unroll 8
    for (int p = 0; p < 128; p++) s += xp[(size_t)p * CDIM];
    g_partial[(b * 32 + j) * CDIM + c] = s;
}

// ---------------- 2) q = pooled @ Wq + bq -----------------------------------
__global__ void q_kernel(const float* __restrict__ Wq, const float* __restrict__ bq) {
    int b = blockIdx.x, t = threadIdx.x;
    __shared__ float sp[CDIM];
    float s = 0.f;
#pragma unroll
    for (int j = 0; j < 32; j++) s += g_partial[(b * 32 + j) * CDIM + t];
    sp[t] = s * (1.0f / 4096.0f);
    __syncthreads();
    float acc = bq[t];
#pragma unroll 8
    for (int c = 0; c < CDIM; c++) acc += sp[c] * Wq[c * 512 + t];
    g_q[b * 512 + t] = acc;
}

// ---------------- 3) qW[b,n,c] = scale * sum_k Wk[c, n*64+k] q[b,n,k] ------
__global__ void qw_kernel(const float* __restrict__ Wk) {
    int b = blockIdx.x, n = blockIdx.y, c = threadIdx.x;
    __shared__ float sq[64];
    if (c < 64) sq[c] = g_q[b * 512 + n * 64 + c];
    __syncthreads();
    const float* wr = Wk + (size_t)c * 512 + n * 64;
    float acc = 0.f;
#pragma unroll
    for (int k = 0; k < 64; k++) acc += sq[k] * wr[k];
    g_qW[(b * 8 + n) * 512 + c] = acc * 0.125f;
}

// ---------------- 4) scores: 128 px/block, 32-col chunks -------------------
__global__ __launch_bounds__(128) void score_kernel(const float* __restrict__ x) {
    extern __shared__ float sdyn[];
    float* sqw = sdyn;            // [8][512]
    float* xs  = sdyn + 4096;     // [128][36]
    int b = blockIdx.x, tid = threadIdx.x;
    int p0 = blockIdx.y * 128;

    for (int i = tid; i < 4096; i += 128)
        sqw[i] = g_qW[(size_t)b * 4096 + i];

    float acc[8] = {0.f, 0.f, 0.f, 0.f, 0.f, 0.f, 0.f, 0.f};

    for (int ch = 0; ch < 16; ch++) {
        __syncthreads();
#pragma unroll
        for (int i = 0; i < 8; i++) {
            int idx = tid + i * 128;
            int p = idx >> 3, c4 = idx & 7;
            *(float4*)(xs + p * 36 + c4 * 4) =
                *(const float4*)(x + ((size_t)b * PIX + p0 + p) * CDIM + ch * 32 + c4 * 4);
        }
        __syncthreads();
#pragma unroll
        for (int c4 = 0; c4 < 8; c4++) {
            float4 xv = *(const float4*)(xs + tid * 36 + c4 * 4);
#pragma unroll
            for (int n = 0; n < 8; n++) {
                float4 w = *(const float4*)(sqw + n * 512 + ch * 32 + c4 * 4);
                acc[n] += xv.x * w.x + xv.y * w.y + xv.z * w.z + xv.w * w.w;
            }
        }
    }
#pragma unroll
    for (int n = 0; n < 8; n++)
        g_S[(size_t)(b * 8 + n) * PIX + p0 + tid] = acc[n];
}

// ---------------- 5) dual softmax per (b,n), write transposed layouts ------
__global__ __launch_bounds__(256) void softmax_kernel() {
    int bn = blockIdx.x;
    int b = bn >> 3, n = bn & 7;
    int tid = threadIdx.x, w = tid >> 5, l = tid & 31;
    __shared__ float ss[4096];
    for (int i = tid; i < 4096; i += 256) ss[i] = g_S[(size_t)bn * 4096 + i];
    __syncthreads();

    for (int h = w; h < 64; h += 8) {
        float x0 = ss[h * 64 + l], x1 = ss[h * 64 + 32 + l];
        float m = fmaxf(x0, x1);
#pragma unroll
        for (int o = 16; o > 0; o >>= 1)
            m = fmaxf(m, __shfl_xor_sync(0xffffffffu, m, o));
        float e0 = __expf(x0 - m), e1 = __expf(x1 - m);
        float sum = e0 + e1;
#pragma unroll
        for (int o = 16; o > 0; o >>= 1)
            sum += __shfl_xor_sync(0xffffffffu, sum, o);
        float inv = 1.0f / sum;
        float* dst = g_ah + ((size_t)(b * 64 + h) * 8 + n) * 64;
        dst[l] = e0 * inv;
        dst[32 + l] = e1 * inv;
    }

    if (tid < 64) {
        int c = tid;
        float m = -1e30f;
#pragma unroll 8
        for (int h = 0; h < 64; h++) m = fmaxf(m, ss[h * 64 + c]);
        float sum = 0.f;
#pragma unroll 8
        for (int h = 0; h < 64; h++) sum += __expf(ss[h * 64 + c] - m);
        float inv = 1.0f / sum;
        float* dst = g_av + ((size_t)(b * 64 + c) * 8 + n) * 64;
#pragma unroll 8
        for (int h = 0; h < 64; h++)
            dst[h] = __expf(ss[h * 64 + c] - m) * inv;
    }
}

// ---------------- 6) y_h / y_v: weighted sums of x rows --------------------
__global__ __launch_bounds__(128) void y_kernel(const float* __restrict__ x) {
    int b = blockIdx.x, s = blockIdx.y, path = blockIdx.z;
    int tid = threadIdx.x;
    __shared__ float sa[512];
    const float* asrc = (path ? g_av : g_ah) + (size_t)(b * 64 + s) * 512;
    for (int i = tid; i < 512; i += 128) sa[i] = asrc[i];
    __syncthreads();

    size_t base = (size_t)b * PIX * CDIM +
                  (path ? (size_t)s * CDIM : (size_t)s * 64 * CDIM);
    size_t stride4 = (path ? (size_t)64 * CDIM : (size_t)CDIM) / 4;
    const float4* xp = (const float4*)(x) + base / 4 + tid;

    float4 acc[8];
#pragma unroll
    for (int n = 0; n < 8; n++) acc[n] = make_float4(0.f, 0.f, 0.f, 0.f);

#pragma unroll 8
    for (int j = 0; j < 64; j++) {
        float4 xv = xp[j * stride4];
#pragma unroll
        for (int n = 0; n < 8; n++) {
            float f = sa[n * 64 + j];
            acc[n].x += f * xv.x;
            acc[n].y += f * xv.y;
            acc[n].z += f * xv.z;
            acc[n].w += f * xv.w;
        }
    }
    float* yout = path ? g_yv : g_yh;
#pragma unroll
    for (int n = 0; n < 8; n++)
        ((float4*)(yout + ((size_t)(n * 1024 + b * 64 + s)) * 512))[tid] = acc[n];
}

// ---------------- 7) aproj via tf32 mma: A = Y @ Wv_n + bv ------------------
// grid (n, b, path), 256 thr = 8 warps. Warp: rows wm*16..+16, cols (wid&1)*32..+32.
// 2-term tf32 split in registers (hi + exact residual); 3 products, fp32 accum.
__global__ __launch_bounds__(256) void aproj_tf32(
    const float* __restrict__ Wv, const float* __restrict__ bv)
{
    __shared__ float sY[64 * 36];   // [64][36] pad -> conflict-free frag loads
    __shared__ float sW[32 * 72];   // [32][72]
    int n = blockIdx.x, b = blockIdx.y, path = blockIdx.z;
    const float* Y = (path ? g_yv : g_yh) + ((size_t)(n * 1024 + b * 64)) * 512;
    float* outp = (path ? g_Av : g_Ah) + (size_t)(b * 8 + n) * 4096;

    int tid = threadIdx.x, lane = tid & 31, wid = tid >> 5;
    int wm = wid >> 1;               // m-tile 0..3 (16 rows)
    int wnb = (wid & 1) * 32;        // col base 0 or 32
    int lr = lane >> 2, lc = lane & 3;

    float acc[4][4];
#pragma unroll
    for (int i = 0; i < 4; i++)
#pragma unroll
        for (int j = 0; j < 4; j++) acc[i][j] = 0.f;

    for (int k0 = 0; k0 < 512; k0 += 32) {
        // stage Y[64 x 32] and W[32 x 64]
#pragma unroll
        for (int i = 0; i < 2; i++) {
            int idx = tid + i * 256;            // 0..511
            int r = idx >> 3, c4 = idx & 7;
            *(float4*)(sY + r * 36 + c4 * 4) =
                *(const float4*)(Y + (size_t)r * 512 + k0 + c4 * 4);
        }
#pragma unroll
        for (int i = 0; i < 2; i++) {
            int idx = tid + i * 256;
            int r = idx >> 4, c4 = idx & 15;
            *(float4*)(sW + r * 72 + c4 * 4) =
                *(const float4*)(Wv + (size_t)(k0 + r) * 512 + n * 64 + c4 * 4);
        }
        __syncthreads();

#pragma unroll
        for (int ks = 0; ks < 4; ks++) {
            int kk = ks * 8;
            // A fragment (m16 x k8) + split
            float a0 = sY[(wm * 16 + lr) * 36 + kk + lc];
            float a1 = sY[(wm * 16 + lr + 8) * 36 + kk + lc];
            float a2 = sY[(wm * 16 + lr) * 36 + kk + lc + 4];
            float a3 = sY[(wm * 16 + lr + 8) * 36 + kk + lc + 4];
            uint32_t ahi[4] = {f2tf32(a0), f2tf32(a1), f2tf32(a2), f2tf32(a3)};
            uint32_t alo[4] = {
                f2tf32(a0 - __uint_as_float(ahi[0])),
                f2tf32(a1 - __uint_as_float(ahi[1])),
                f2tf32(a2 - __uint_as_float(ahi[2])),
                f2tf32(a3 - __uint_as_float(ahi[3]))};
#pragma unroll
            for (int nt = 0; nt < 4; nt++) {
                int nb = wnb + nt * 8;
                float b0 = sW[(kk + lc) * 72 + nb + lr];
                float b1 = sW[(kk + lc + 4) * 72 + nb + lr];
                uint32_t bhi[2] = {f2tf32(b0), f2tf32(b1)};
                uint32_t blo[2] = {
                    f2tf32(b0 - __uint_as_float(bhi[0])),
                    f2tf32(b1 - __uint_as_float(bhi[1]))};
                mma_tf32(acc[nt], ahi, bhi);
                mma_tf32(acc[nt], alo, bhi);
                mma_tf32(acc[nt], ahi, blo);
            }
        }
        __syncthreads();
    }

#pragma unroll
    for (int nt = 0; nt < 4; nt++) {
        int col = wnb + nt * 8 + lc * 2;
        float b0 = bv[n * 64 + col], b1 = bv[n * 64 + col + 1];
        int r0 = wm * 16 + lr;
        *(float2*)(outp + (size_t)r0 * 64 + col) =
            make_float2(acc[nt][0] + b0, acc[nt][1] + b1);
        *(float2*)(outp + (size_t)(r0 + 8) * 64 + col) =
            make_float2(acc[nt][2] + b0, acc[nt][3] + b1);
    }
}

// ---------------- 8) Wext = [hi(Wo); hi(Wo); lo(Wo)] -----------------------
__global__ void wext_kernel(const float* __restrict__ Wo) {
    int r = blockIdx.x, n = threadIdx.x;
    int src = (r < 128) ? (r & 63) : (r - 128);
    float v = Wo[(size_t)src * 512 + n];
    __nv_bfloat16 hi = __float2bfloat16(v);
    g_Wext[r * 512 + n] = (r < 128) ? hi
                                    : __float2bfloat16(v - __bfloat162float(hi));
}

// ---------------- 9) combine -> Aext bf16 [hi|lo|hi] ------------------------
__global__ __launch_bounds__(512) void combine_kernel() {
    int b = blockIdx.x >> 6, h = blockIdx.x & 63;
    int tid = threadIdx.x;
    __shared__ float sAh[NHEAD * DVV];
    {
        int n = tid >> 6, v = tid & 63;
        sAh[tid] = g_Ah[((size_t)(b * 8 + n) * 64 + h) * 64 + v];
    }
    __syncthreads();
    int v = tid & 63, wg = tid >> 6;
    for (int wc = wg; wc < 64; wc += 8) {
        float acc = 0.f;
#pragma unroll
        for (int n = 0; n < NHEAD; n++)
            acc += sAh[n * 64 + v] *
                   g_Av[((size_t)(b * 8 + n) * 64 + wc) * 64 + v];
        size_t row = ((size_t)(b * 64 + h)) * 64 + wc;
        __nv_bfloat16 hi = __float2bfloat16(acc);
        __nv_bfloat16 lo = __float2bfloat16(acc - __bfloat162float(hi));
        g_Aext[row * 192 + v]       = hi;
        g_Aext[row * 192 + 64 + v]  = lo;
        g_Aext[row * 192 + 128 + v] = hi;
    }
}

// ---------------- 10) bf16 mma.sync GEMM: C = Aext @ Wext + bias -----------
__global__ __launch_bounds__(256) void mma_gemm_out(
    const float* __restrict__ bias, float* __restrict__ C)
{
    __shared__ __align__(16) __nv_bfloat16 smA[128 * 72];
    __shared__ __align__(16) __nv_bfloat16 smB[64 * 136];
    int tid = threadIdx.x, lane = tid & 31, wid = tid >> 5;
    int wm = wid >> 2, wn = wid & 3;
    size_t m0 = (size_t)blockIdx.y * 128;
    int n0 = blockIdx.x * 128;

    float acc[4][4][4];
#pragma unroll
    for (int i = 0; i < 4; i++)
#pragma unroll
        for (int j = 0; j < 4; j++)
#pragma unroll
            for (int k = 0; k < 4; k++) acc[i][j][k] = 0.f;

    for (int kc = 0; kc < 192; kc += 64) {
#pragma unroll
        for (int i = 0; i < 4; i++) {
            int idx = tid + i * 256;
            int r = idx >> 3, c8 = idx & 7;
            *(float4*)(smA + r * 72 + c8 * 8) =
                *(const float4*)(g_Aext + (m0 + r) * 192 + kc + c8 * 8);
        }
#pragma unroll
        for (int i = 0; i < 4; i++) {
            int idx = tid + i * 256;
            int r = idx >> 4, c8 = idx & 15;
            *(float4*)(smB + r * 136 + c8 * 8) =
                *(const float4*)(g_Wext + (size_t)(kc + r) * 512 + n0 + c8 * 8);
        }
        __syncthreads();

#pragma unroll
        for (int ks = 0; ks < 4; ks++) {
            uint32_t af[4][4];
#pragma unroll
            for (int mi = 0; mi < 4; mi++) {
                uint32_t addr = smem_u32(
                    smA + (wm * 64 + mi * 16 + (lane & 15)) * 72 +
                    ks * 16 + (lane >> 4) * 8);
                asm volatile(
                    "ldmatrix.sync.aligned.m8n8.x4.shared.b16 {%0,%1,%2,%3}, [%4];"
                    : "=r"(af[mi][0]), "=r"(af[mi][1]),
                      "=r"(af[mi][2]), "=r"(af[mi][3])
                    : "r"(addr));
            }
            uint32_t bfr[2][4];
#pragma unroll
            for (int bi = 0; bi < 2; bi++) {
                int nb = wn * 32 + bi * 16;
                uint32_t addr = smem_u32(
                    smB + (ks * 16 + (lane & 7) + ((lane >> 3) & 1) * 8) * 136 +
                    nb + (lane >> 4) * 8);
                asm volatile(
                    "ldmatrix.sync.aligned.m8n8.x4.trans.shared.b16 {%0,%1,%2,%3}, [%4];"
                    : "=r"(bfr[bi][0]), "=r"(bfr[bi][1]),
                      "=r"(bfr[bi][2]), "=r"(bfr[bi][3])
                    : "r"(addr));
            }
#pragma unroll
            for (int mi = 0; mi < 4; mi++) {
#pragma unroll
                for (int ni = 0; ni < 4; ni++) {
                    uint32_t b0 = bfr[ni >> 1][(ni & 1) * 2];
                    uint32_t b1 = bfr[ni >> 1][(ni & 1) * 2 + 1];
                    asm volatile(
                        "mma.sync.aligned.m16n8k16.row.col.f32.bf16.bf16.f32 "
                        "{%0,%1,%2,%3}, {%4,%5,%6,%7}, {%8,%9}, {%0,%1,%2,%3};"
                        : "+f"(acc[mi][ni][0]), "+f"(acc[mi][ni][1]),
                          "+f"(acc[mi][ni][2]), "+f"(acc[mi][ni][3])
                        : "r"(af[mi][0]), "r"(af[mi][1]),
                          "r"(af[mi][2]), "r"(af[mi][3]),
                          "r"(b0), "r"(b1));
                }
            }
        }
        __syncthreads();
    }

    int g = lane >> 2, t = lane & 3;
#pragma unroll
    for (int mi = 0; mi < 4; mi++) {
#pragma unroll
        for (int ni = 0; ni < 4; ni++) {
            size_t row = m0 + wm * 64 + mi * 16 + g;
            int col = n0 + wn * 32 + ni * 8 + t * 2;
            float b0 = bias[col], b1 = bias[col + 1];
            float2 o0 = {acc[mi][ni][0] + b0, acc[mi][ni][1] + b1};
            float2 o1 = {acc[mi][ni][2] + b0, acc[mi][ni][3] + b1};
            *(float2*)(C + row * 512 + col) = o0;
            *(float2*)(C + (row + 8) * 512 + col) = o1;
        }
    }
}

// ---------------- launch ----------------------------------------------------
extern "C" void kernel_launch(void* const* d_in, const int* in_sizes, int n_in,
                              void* d_out, int out_size) {
    const float* x  = (const float*)d_in[0];
    const float* Wq = (const float*)d_in[1];
    const float* bq = (const float*)d_in[2];
    const float* Wk = (const float*)d_in[3];
    const float* bk = (const float*)d_in[4];  (void)bk;  // cancels in softmax
    const float* Wv = (const float*)d_in[5];
    const float* bv = (const float*)d_in[6];
    const float* Wo = (const float*)d_in[7];
    const float* bo = (const float*)d_in[8];
    float* out = (float*)d_out;

    const int SCORE_SMEM = (4096 + 128 * 36) * 4;   // 34816 B
    cudaFuncSetAttribute(score_kernel,
                         cudaFuncAttributeMaxDynamicSharedMemorySize, SCORE_SMEM);

    pool_kernel<<<dim3(BSZ, 32), 512>>>(x);
    q_kernel<<<BSZ, 512>>>(Wq, bq);
    qw_kernel<<<dim3(BSZ, NHEAD), 512>>>(Wk);
    wext_kernel<<<192, 512>>>(Wo);
    score_kernel<<<dim3(BSZ, 32), 128, SCORE_SMEM>>>(x);
    softmax_kernel<<<BSZ * NHEAD, 256>>>();
    y_kernel<<<dim3(BSZ, 64, 2), 128>>>(x);
    aproj_tf32<<<dim3(NHEAD, BSZ, 2), 256>>>(Wv, bv);
    combine_kernel<<<BSZ * HH, 512>>>();
    mma_gemm_out<<<dim3(4, 512), 256>>>(bo, out);
}